// round 1
// baseline (speedup 1.0000x reference)
#include <cuda_runtime.h>
#include <cstddef>

#define BB 4
#define LL 4096
#define DD 1024
#define NK 256
#define KD 64
#define NH 4
#define CC 128
#define JJ 32      // LL/CC
#define NCH 16     // BB*NH channels per head
#define XT 192     // trajectory length (CC + KD)

// ---------------- device scratch (no allocations allowed) ----------------
__device__ float g_anorm[NK];
__device__ int   g_flag;
__device__ float g_X [NK][XT][KD];     // x_t = A^t e0
__device__ float g_Nt[NK][CC][KD];     // Nt[sigma][i] = (A^{C-1-sigma} b)[i]
__device__ float g_k [NK][CC];         // k[l] = c . A^l b , l < C
__device__ float g_M [NK][CC][KD];     // M[tau][i] = (c^T A^{tau+1})[i]
__device__ float g_P [NK][KD][KD];     // P = A^C
__device__ float g_G [NK][JJ][NCH][KD];
__device__ float g_H [NK][JJ][NCH][KD]; // H_{j-1} (state BEFORE chunk j)

// ---------------- 1) per-head L1 norm of a ----------------
__global__ void k_norm(const float* __restrict__ a) {
    int h = blockIdx.x, i = threadIdx.x;
    float v = fabsf(a[h * KD + i]);
    #pragma unroll
    for (int o = 16; o; o >>= 1) v += __shfl_down_sync(0xffffffffu, v, o);
    __shared__ float sm[2];
    if ((i & 31) == 0) sm[i >> 5] = v;
    __syncthreads();
    if (i == 0) g_anorm[h] = sm[0] + sm[1];
}

// ---------------- 2) global mean(|a_norm|) > eps flag ----------------
__global__ void k_flag() {
    int t = threadIdx.x;
    float v = g_anorm[t];
    __shared__ float sm[8];
    #pragma unroll
    for (int o = 16; o; o >>= 1) v += __shfl_down_sync(0xffffffffu, v, o);
    if ((t & 31) == 0) sm[t >> 5] = v;
    __syncthreads();
    if (t == 0) {
        float s = 0.f;
        #pragma unroll
        for (int w = 0; w < 8; w++) s += sm[w];
        g_flag = (s / (float)NK > 1e-4f) ? 1 : 0;
    }
}

// ---------------- 3) per-head precompute: trajectories -> Nt, k, M, P ----
__global__ __launch_bounds__(256) void k_precomp(const float* __restrict__ a,
                                                 const float* __restrict__ b,
                                                 const float* __restrict__ c) {
    int h = blockIdx.x, tid = threadIdx.x;
    __shared__ float an[KD], cs[KD], bs[KD], s[XT], kk[CC];
    if (tid < KD) {
        float av = a[h * KD + tid];
        an[tid] = g_flag ? (av / g_anorm[h]) : av;
        cs[tid] = c[h * KD + tid];
        bs[tid] = b[h * KD + tid];
    }
    __syncthreads();
    int wid = tid >> 5, lane = tid & 31;
    if (wid == 0) {
        // x_t = A^t e0, t = 0..XT-1
        float x0 = (lane == 0) ? 1.f : 0.f, x1 = 0.f;
        float alo = an[lane], ahi = an[lane + 32];
        g_X[h][0][lane] = x0; g_X[h][0][lane + 32] = x1;
        for (int t = 1; t < XT; t++) {
            float last = __shfl_sync(0xffffffffu, x1, 31);
            float top  = __shfl_sync(0xffffffffu, x0, 31);
            float sx0  = __shfl_up_sync(0xffffffffu, x0, 1);
            float sx1  = __shfl_up_sync(0xffffffffu, x1, 1);
            if (lane == 0) { sx0 = 0.f; sx1 = top; }
            x0 = fmaf(alo, last, sx0);
            x1 = fmaf(ahi, last, sx1);
            g_X[h][t][lane] = x0; g_X[h][t][lane + 32] = x1;
        }
    } else if (wid == 1) {
        // w_t = A^t b, t = 0..CC-1 ; Nt[C-1-t] = w_t
        float x0 = bs[lane], x1 = bs[lane + 32];
        float alo = an[lane], ahi = an[lane + 32];
        g_Nt[h][CC - 1][lane] = x0; g_Nt[h][CC - 1][lane + 32] = x1;
        for (int t = 1; t < CC; t++) {
            float last = __shfl_sync(0xffffffffu, x1, 31);
            float top  = __shfl_sync(0xffffffffu, x0, 31);
            float sx0  = __shfl_up_sync(0xffffffffu, x0, 1);
            float sx1  = __shfl_up_sync(0xffffffffu, x1, 1);
            if (lane == 0) { sx0 = 0.f; sx1 = top; }
            x0 = fmaf(alo, last, sx0);
            x1 = fmaf(ahi, last, sx1);
            g_Nt[h][CC - 1 - t][lane] = x0; g_Nt[h][CC - 1 - t][lane + 32] = x1;
        }
    }
    __syncthreads();
    // s_t = c . x_t  (t = 1..XT-1)
    {
        int t = tid + 1;
        if (t < XT) {
            float acc = 0.f;
            #pragma unroll 16
            for (int i = 0; i < KD; i++) acc = fmaf(cs[i], g_X[h][t][i], acc);
            s[t] = acc;
        }
    }
    // k[l] = c . w_l
    if (tid < CC) {
        float acc = 0.f;
        #pragma unroll 16
        for (int i = 0; i < KD; i++) acc = fmaf(cs[i], g_Nt[h][CC - 1 - tid][i], acc);
        kk[tid] = acc;
    }
    __syncthreads();
    if (tid < CC) g_k[h][tid] = kk[tid];
    for (int idx = tid; idx < CC * KD; idx += 256) {
        int tau = idx >> 6, i2 = idx & 63;
        g_M[h][tau][i2] = s[tau + 1 + i2];       // M[tau][i] = c.A^{tau+1+i} e0
    }
    for (int idx = tid; idx < KD * KD; idx += 256) {
        int i2 = idx >> 6, j2 = idx & 63;
        g_P[h][i2][j2] = g_X[h][CC + j2][i2];    // P[:,j] = x_{C+j}
    }
}

// ---------------- 4) G[h][j][c][:] = Nt^T * u_chunk ----------------
__global__ __launch_bounds__(256) void k_g(const float* __restrict__ u) {
    int j = blockIdx.x, h = blockIdx.y, tid = threadIdx.x;
    __shared__ float Us[CC][NCH];
    __shared__ float Nts[CC][KD];
    for (int idx = tid; idx < CC * NCH; idx += 256) {
        int sg = idx >> 4, cch = idx & 15;
        int bb = cch >> 2, r = cch & 3;
        Us[sg][cch] = u[((size_t)(bb * LL + j * CC + sg)) * DD + h * NH + r];
    }
    for (int idx = tid; idx < CC * KD; idx += 256)
        Nts[idx >> 6][idx & 63] = g_Nt[h][idx >> 6][idx & 63];
    __syncthreads();
    int i2 = tid & 63, cg = tid >> 6;
    float a0 = 0.f, a1 = 0.f, a2 = 0.f, a3 = 0.f;
    #pragma unroll 4
    for (int sg = 0; sg < CC; sg++) {
        float nv = Nts[sg][i2];
        a0 = fmaf(nv, Us[sg][cg * 4 + 0], a0);
        a1 = fmaf(nv, Us[sg][cg * 4 + 1], a1);
        a2 = fmaf(nv, Us[sg][cg * 4 + 2], a2);
        a3 = fmaf(nv, Us[sg][cg * 4 + 3], a3);
    }
    g_G[h][j][cg * 4 + 0][i2] = a0;
    g_G[h][j][cg * 4 + 1][i2] = a1;
    g_G[h][j][cg * 4 + 2][i2] = a2;
    g_G[h][j][cg * 4 + 3][i2] = a3;
}

// ---------------- 5) scan: H_j = P H_{j-1} + G_j (store H_{j-1}) --------
__global__ __launch_bounds__(64) void k_scan() {
    int h = blockIdx.x >> 4, cch = blockIdx.x & 15, i = threadIdx.x;
    __shared__ float Ps[KD][KD + 1];
    __shared__ float hs[KD];
    for (int idx = i; idx < KD * KD; idx += 64)
        Ps[idx >> 6][idx & 63] = g_P[h][idx >> 6][idx & 63];
    float hv = 0.f;
    for (int j = 0; j < JJ; j++) {
        g_H[h][j][cch][i] = hv;
        hs[i] = hv;
        __syncthreads();
        float acc = g_G[h][j][cch][i];
        #pragma unroll
        for (int kq = 0; kq < KD; kq++) acc = fmaf(Ps[i][kq], hs[kq], acc);
        __syncthreads();
        hv = acc;
    }
}

// ---------------- 6) y = Toeplitz(k) u_j + M H_{j-1} ----------------
#define KTS_STRIDE (CC + 1)
#define MS_STRIDE  (KD + 1)
#define HS_STRIDE  (KD + 1)
#define SMEM_KY ((CC * KTS_STRIDE + CC * MS_STRIDE + CC * NCH + NCH * HS_STRIDE) * sizeof(float))

__global__ __launch_bounds__(256) void k_y(const float* __restrict__ u,
                                           float* __restrict__ y) {
    extern __shared__ float sm[];
    float* Kts = sm;                              // [CC][CC+1]
    float* Ms  = Kts + CC * KTS_STRIDE;           // [CC][KD+1]
    float* Us  = Ms  + CC * MS_STRIDE;            // [CC][NCH]
    float* Hs  = Us  + CC * NCH;                  // [NCH][KD+1]
    __shared__ float kk[CC];
    int h = blockIdx.x, tid = threadIdx.x;
    if (tid < CC) kk[tid] = g_k[h][tid];
    __syncthreads();
    for (int idx = tid; idx < CC * CC; idx += 256) {
        int tau = idx >> 7, sg = idx & 127;
        Kts[tau * KTS_STRIDE + sg] = (sg <= tau) ? kk[tau - sg] : 0.f;
    }
    for (int idx = tid; idx < CC * KD; idx += 256) {
        int tau = idx >> 6, i2 = idx & 63;
        Ms[tau * MS_STRIDE + i2] = g_M[h][tau][i2];
    }
    int cch = tid & 15, t0 = (tid >> 4) & 15;
    int bb = cch >> 2, r = cch & 3;
    size_t ybase = (size_t)bb * LL * DD + (size_t)(h * NH + r);
    for (int j = 0; j < JJ; j++) {
        __syncthreads();
        for (int idx = tid; idx < CC * NCH; idx += 256) {
            int sg = idx >> 4, c2 = idx & 15;
            int b2 = c2 >> 2, r2 = c2 & 3;
            Us[sg * NCH + c2] = u[((size_t)(b2 * LL + j * CC + sg)) * DD + h * NH + r2];
        }
        for (int idx = tid; idx < NCH * KD; idx += 256) {
            int c2 = idx >> 6, i2 = idx & 63;
            Hs[c2 * HS_STRIDE + i2] = g_H[h][j][c2][i2];
        }
        __syncthreads();
        float acc[8];
        #pragma unroll
        for (int q = 0; q < 8; q++) acc[q] = 0.f;
        // inter-chunk: M @ H_{j-1}
        #pragma unroll 8
        for (int i2 = 0; i2 < KD; i2++) {
            float hvv = Hs[cch * HS_STRIDE + i2];
            #pragma unroll
            for (int q = 0; q < 8; q++)
                acc[q] = fmaf(Ms[(t0 + 16 * q) * MS_STRIDE + i2], hvv, acc[q]);
        }
        // intra-chunk: lower-triangular Toeplitz @ u_j
        #pragma unroll
        for (int sb = 0; sb < 8; sb++) {
            #pragma unroll
            for (int ss = 0; ss < 16; ss++) {
                int sg = sb * 16 + ss;
                float uv = Us[sg * NCH + cch];
                if (ss <= t0)
                    acc[sb] = fmaf(Kts[(t0 + 16 * sb) * KTS_STRIDE + sg], uv, acc[sb]);
                #pragma unroll
                for (int q = sb + 1; q < 8; q++)
                    acc[q] = fmaf(Kts[(t0 + 16 * q) * KTS_STRIDE + sg], uv, acc[q]);
            }
        }
        size_t tbase = (size_t)j * CC;
        #pragma unroll
        for (int q = 0; q < 8; q++) {
            int tau = t0 + 16 * q;
            y[ybase + (tbase + tau) * DD] = acc[q];
        }
    }
}

// ---------------- launch ----------------
extern "C" void kernel_launch(void* const* d_in, const int* in_sizes, int n_in,
                              void* d_out, int out_size) {
    const float* u = (const float*)d_in[0];
    const float* a = (const float*)d_in[1];
    const float* b = (const float*)d_in[2];
    const float* c = (const float*)d_in[3];
    float* y = (float*)d_out;

    k_norm<<<NK, KD>>>(a);
    k_flag<<<1, NK>>>();
    k_precomp<<<NK, 256>>>(a, b, c);
    k_g<<<dim3(JJ, NK), 256>>>(u);
    k_scan<<<NK * NCH, 64>>>();
    cudaFuncSetAttribute(k_y, cudaFuncAttributeMaxDynamicSharedMemorySize, (int)SMEM_KY);
    k_y<<<NK, 256, SMEM_KY>>>(u, y);
}

// round 2
// speedup vs baseline: 3.5945x; 3.5945x over previous
#include <cuda_runtime.h>
#include <cstddef>

#define BB 4
#define LL 4096
#define DD 1024
#define NK 256
#define KD 64
#define NH 4
#define CC 128
#define JJ 32      // LL/CC
#define NCH 16     // BB*NH channels per head
#define XT 192     // trajectory length (CC + KD)

// ---------------- device scratch (no allocations allowed) ----------------
__device__ float g_anorm[NK];
__device__ int   g_flag;
__device__ float g_X [NK][XT][KD];     // x_t = A^t e0
__device__ float g_Nt[NK][CC][KD];     // Nt[sigma][i] = (A^{C-1-sigma} b)[i]
__device__ float g_k [NK][CC];         // k[l] = c . A^l b , l < C
__device__ float g_s [NK][XT];         // s[t] = c . A^t e0
__device__ float g_P [NK][KD][KD];     // P = A^C
__device__ float g_G [NK][JJ][KD][NCH];
__device__ float g_H [NK][JJ][KD][NCH]; // H_{j-1} (state BEFORE chunk j)

// ---------------- 1) per-head L1 norm of a ----------------
__global__ void k_norm(const float* __restrict__ a) {
    int h = blockIdx.x, i = threadIdx.x;
    float v = fabsf(a[h * KD + i]);
    #pragma unroll
    for (int o = 16; o; o >>= 1) v += __shfl_down_sync(0xffffffffu, v, o);
    __shared__ float sm[2];
    if ((i & 31) == 0) sm[i >> 5] = v;
    __syncthreads();
    if (i == 0) g_anorm[h] = sm[0] + sm[1];
}

// ---------------- 2) global mean(|a_norm|) > eps flag ----------------
__global__ void k_flag() {
    int t = threadIdx.x;
    float v = g_anorm[t];
    __shared__ float sm[8];
    #pragma unroll
    for (int o = 16; o; o >>= 1) v += __shfl_down_sync(0xffffffffu, v, o);
    if ((t & 31) == 0) sm[t >> 5] = v;
    __syncthreads();
    if (t == 0) {
        float s = 0.f;
        #pragma unroll
        for (int w = 0; w < 8; w++) s += sm[w];
        g_flag = (s / (float)NK > 1e-4f) ? 1 : 0;
    }
}

// ---------------- 3) per-head precompute: trajectories -> Nt, k, s, P ----
__global__ __launch_bounds__(256) void k_precomp(const float* __restrict__ a,
                                                 const float* __restrict__ b,
                                                 const float* __restrict__ c) {
    int h = blockIdx.x, tid = threadIdx.x;
    __shared__ float an[KD], cs[KD], bs[KD];
    if (tid < KD) {
        float av = a[h * KD + tid];
        an[tid] = g_flag ? (av / g_anorm[h]) : av;
        cs[tid] = c[h * KD + tid];
        bs[tid] = b[h * KD + tid];
    }
    __syncthreads();
    int wid = tid >> 5, lane = tid & 31;
    if (wid == 0) {
        // x_t = A^t e0, t = 0..XT-1
        float x0 = (lane == 0) ? 1.f : 0.f, x1 = 0.f;
        float alo = an[lane], ahi = an[lane + 32];
        g_X[h][0][lane] = x0; g_X[h][0][lane + 32] = x1;
        for (int t = 1; t < XT; t++) {
            float last = __shfl_sync(0xffffffffu, x1, 31);
            float top  = __shfl_sync(0xffffffffu, x0, 31);
            float sx0  = __shfl_up_sync(0xffffffffu, x0, 1);
            float sx1  = __shfl_up_sync(0xffffffffu, x1, 1);
            if (lane == 0) { sx0 = 0.f; sx1 = top; }
            x0 = fmaf(alo, last, sx0);
            x1 = fmaf(ahi, last, sx1);
            g_X[h][t][lane] = x0; g_X[h][t][lane + 32] = x1;
        }
    } else if (wid == 1) {
        // w_t = A^t b, t = 0..CC-1 ; Nt[C-1-t] = w_t
        float x0 = bs[lane], x1 = bs[lane + 32];
        float alo = an[lane], ahi = an[lane + 32];
        g_Nt[h][CC - 1][lane] = x0; g_Nt[h][CC - 1][lane + 32] = x1;
        for (int t = 1; t < CC; t++) {
            float last = __shfl_sync(0xffffffffu, x1, 31);
            float top  = __shfl_sync(0xffffffffu, x0, 31);
            float sx0  = __shfl_up_sync(0xffffffffu, x0, 1);
            float sx1  = __shfl_up_sync(0xffffffffu, x1, 1);
            if (lane == 0) { sx0 = 0.f; sx1 = top; }
            x0 = fmaf(alo, last, sx0);
            x1 = fmaf(ahi, last, sx1);
            g_Nt[h][CC - 1 - t][lane] = x0; g_Nt[h][CC - 1 - t][lane + 32] = x1;
        }
    }
    __syncthreads();
    // s_t = c . x_t  (t = 1..XT-1)
    {
        int t = tid;
        if (t >= 1 && t < XT) {
            float acc = 0.f;
            #pragma unroll 16
            for (int i = 0; i < KD; i++) acc = fmaf(cs[i], g_X[h][t][i], acc);
            g_s[h][t] = acc;
        }
        if (t == 0) g_s[h][0] = 0.f;
    }
    // k[l] = c . w_l
    if (tid < CC) {
        float acc = 0.f;
        #pragma unroll 16
        for (int i = 0; i < KD; i++) acc = fmaf(cs[i], g_Nt[h][CC - 1 - tid][i], acc);
        g_k[h][tid] = acc;
    }
    // P[:,j2] = x_{C+j2}
    for (int idx = tid; idx < KD * KD; idx += 256) {
        int i2 = idx >> 6, j2 = idx & 63;
        g_P[h][i2][j2] = g_X[h][CC + j2][i2];
    }
}

// ---------------- 4) G[h][j][i][ch] = Nt^T * u_chunk (4x4 reg tiles) ----
// block = (jq, h); 256 threads = 4 chunk-units x 64 threads (16 igrp x 4 chgrp)
__global__ __launch_bounds__(256) void k_g(const float* __restrict__ u) {
    extern __shared__ float smg[];
    float* Nts = smg;                 // [CC][KD]   = 8192 floats
    float* Usg = smg + CC * KD;       // [4][CC][NCH] = 8192 floats
    int jq = blockIdx.x, h = blockIdx.y, tid = threadIdx.x;
    // load Nt tile (coalesced float4)
    #pragma unroll
    for (int it = 0; it < 8; it++) {
        int idx = tid + 256 * it;                  // < 2048 float4
        int sg = idx >> 4, q = idx & 15;
        *(float4*)&Nts[sg * KD + q * 4] = *(const float4*)&g_Nt[h][sg][q * 4];
    }
    // load 4 chunks of u
    #pragma unroll
    for (int it = 0; it < 8; it++) {
        int idx = tid + 256 * it;                  // < 2048 float4
        int un = idx >> 9, rem = idx & 511;
        int sg = rem >> 2, bb = rem & 3;
        float4 v = *(const float4*)&u[((size_t)(bb * LL + (jq * 4 + un) * CC + sg)) * DD + h * NH];
        *(float4*)&Usg[(un * CC + sg) * NCH + bb * 4] = v;
    }
    __syncthreads();
    int un = tid >> 6, ut = tid & 63;
    int chgrp = ut & 3, igrp = ut >> 2;
    int i0 = igrp * 4, ch0 = chgrp * 4;
    int j = jq * 4 + un;
    float acc[4][4];
    #pragma unroll
    for (int t = 0; t < 4; t++)
        #pragma unroll
        for (int q = 0; q < 4; q++) acc[t][q] = 0.f;
    const float* Un = Usg + un * CC * NCH;
    #pragma unroll 8
    for (int sg = 0; sg < CC; sg++) {
        float4 nv = *(const float4*)&Nts[sg * KD + i0];
        float4 uv = *(const float4*)&Un[sg * NCH + ch0];
        float nvv[4] = {nv.x, nv.y, nv.z, nv.w};
        float uvv[4] = {uv.x, uv.y, uv.z, uv.w};
        #pragma unroll
        for (int t = 0; t < 4; t++)
            #pragma unroll
            for (int q = 0; q < 4; q++) acc[t][q] = fmaf(nvv[t], uvv[q], acc[t][q]);
    }
    #pragma unroll
    for (int t = 0; t < 4; t++) {
        float4 o = make_float4(acc[t][0], acc[t][1], acc[t][2], acc[t][3]);
        *(float4*)&g_G[h][j][i0 + t][ch0] = o;
    }
}

// ---------------- 5) scan: H_j = P H_{j-1} + G_j (store H_{j-1}) --------
// block = (h*4 + chgrp); 64 threads = i; P row in registers; 4 ch per thread
__global__ __launch_bounds__(64) void k_scan() {
    int h = blockIdx.x >> 2, cq = blockIdx.x & 3, i = threadIdx.x;
    int ch0 = cq * 4;
    float P[KD];
    #pragma unroll
    for (int kq = 0; kq < KD; kq += 4) {
        float4 p = *(const float4*)&g_P[h][i][kq];
        P[kq] = p.x; P[kq + 1] = p.y; P[kq + 2] = p.z; P[kq + 3] = p.w;
    }
    __shared__ float hs[KD][4];
    float hv[4] = {0.f, 0.f, 0.f, 0.f};
    for (int j = 0; j < JJ; j++) {
        float4 hw = make_float4(hv[0], hv[1], hv[2], hv[3]);
        *(float4*)&g_H[h][j][i][ch0] = hw;
        *(float4*)&hs[i][0] = hw;
        __syncthreads();
        float4 g = *(const float4*)&g_G[h][j][i][ch0];
        float acc[4] = {g.x, g.y, g.z, g.w};
        #pragma unroll
        for (int kq = 0; kq < KD; kq++) {
            float4 hk = *(const float4*)&hs[kq][0];
            acc[0] = fmaf(P[kq], hk.x, acc[0]);
            acc[1] = fmaf(P[kq], hk.y, acc[1]);
            acc[2] = fmaf(P[kq], hk.z, acc[2]);
            acc[3] = fmaf(P[kq], hk.w, acc[3]);
        }
        __syncthreads();
        hv[0] = acc[0]; hv[1] = acc[1]; hv[2] = acc[2]; hv[3] = acc[3];
    }
}

// ---------------- 6) y = Toeplitz(k) u_j + Hankel(s) H_{j-1} ------------
// block = (j, h); 128 threads = 32 taugrp x 4 chgrp; 4tau x 4ch reg tile
__global__ __launch_bounds__(128) void k_y(const float* __restrict__ u,
                                           float* __restrict__ y) {
    __shared__ float Us[CC][NCH];      // 8 KB
    __shared__ float Hs[KD][NCH];      // 4 KB
    __shared__ float kkp[2 * CC];      // zero-padded kernel: kkp[128+d]=k[d]
    __shared__ float ssm[XT + 8];      // zero-padded s
    int j = blockIdx.x, h = blockIdx.y, tid = threadIdx.x;
    for (int idx = tid; idx < 2 * CC; idx += 128)
        kkp[idx] = (idx >= CC) ? g_k[h][idx - CC] : 0.f;
    for (int idx = tid; idx < XT + 8; idx += 128)
        ssm[idx] = (idx < XT) ? g_s[h][idx] : 0.f;
    #pragma unroll
    for (int it = 0; it < 4; it++) {
        int idx = tid + 128 * it;                  // < 512 float4
        int sg = idx >> 2, bb = idx & 3;
        float4 v = *(const float4*)&u[((size_t)(bb * LL + j * CC + sg)) * DD + h * NH];
        *(float4*)&Us[sg][bb * 4] = v;
    }
    #pragma unroll
    for (int it = 0; it < 2; it++) {
        int idx = tid + 128 * it;                  // < 256 float4
        int i2 = idx >> 2, bb = idx & 3;
        *(float4*)&Hs[i2][bb * 4] = *(const float4*)&g_H[h][j][i2][bb * 4];
    }
    __syncthreads();
    int chgrp = tid & 3, tgrp = tid >> 2;
    int t0 = tgrp * 4, ch0 = chgrp * 4;
    float acc[4][4];
    #pragma unroll
    for (int t = 0; t < 4; t++)
        #pragma unroll
        for (int q = 0; q < 4; q++) acc[t][q] = 0.f;
    // ---- inter-chunk: Hankel(s) @ H, sliding window over s ----
    {
        float sw0 = ssm[t0 + 1], sw1 = ssm[t0 + 2], sw2 = ssm[t0 + 3], sw3 = ssm[t0 + 4];
        #pragma unroll 16
        for (int i2 = 0; i2 < KD; i2++) {
            float4 hv = *(const float4*)&Hs[i2][ch0];
            acc[0][0] = fmaf(sw0, hv.x, acc[0][0]);
            acc[0][1] = fmaf(sw0, hv.y, acc[0][1]);
            acc[0][2] = fmaf(sw0, hv.z, acc[0][2]);
            acc[0][3] = fmaf(sw0, hv.w, acc[0][3]);
            acc[1][0] = fmaf(sw1, hv.x, acc[1][0]);
            acc[1][1] = fmaf(sw1, hv.y, acc[1][1]);
            acc[1][2] = fmaf(sw1, hv.z, acc[1][2]);
            acc[1][3] = fmaf(sw1, hv.w, acc[1][3]);
            acc[2][0] = fmaf(sw2, hv.x, acc[2][0]);
            acc[2][1] = fmaf(sw2, hv.y, acc[2][1]);
            acc[2][2] = fmaf(sw2, hv.z, acc[2][2]);
            acc[2][3] = fmaf(sw2, hv.w, acc[2][3]);
            acc[3][0] = fmaf(sw3, hv.x, acc[3][0]);
            acc[3][1] = fmaf(sw3, hv.y, acc[3][1]);
            acc[3][2] = fmaf(sw3, hv.z, acc[3][2]);
            acc[3][3] = fmaf(sw3, hv.w, acc[3][3]);
            sw0 = sw1; sw1 = sw2; sw2 = sw3;
            sw3 = ssm[t0 + 5 + i2];
        }
    }
    // ---- intra-chunk: Toeplitz(k) @ u, sliding window over kkp ----
    {
        float kw0 = kkp[CC + t0], kw1 = kkp[CC + t0 + 1],
              kw2 = kkp[CC + t0 + 2], kw3 = kkp[CC + t0 + 3];
        #pragma unroll 16
        for (int sg = 0; sg < CC; sg++) {
            float4 uv = *(const float4*)&Us[sg][ch0];
            acc[0][0] = fmaf(kw0, uv.x, acc[0][0]);
            acc[0][1] = fmaf(kw0, uv.y, acc[0][1]);
            acc[0][2] = fmaf(kw0, uv.z, acc[0][2]);
            acc[0][3] = fmaf(kw0, uv.w, acc[0][3]);
            acc[1][0] = fmaf(kw1, uv.x, acc[1][0]);
            acc[1][1] = fmaf(kw1, uv.y, acc[1][1]);
            acc[1][2] = fmaf(kw1, uv.z, acc[1][2]);
            acc[1][3] = fmaf(kw1, uv.w, acc[1][3]);
            acc[2][0] = fmaf(kw2, uv.x, acc[2][0]);
            acc[2][1] = fmaf(kw2, uv.y, acc[2][1]);
            acc[2][2] = fmaf(kw2, uv.z, acc[2][2]);
            acc[2][3] = fmaf(kw2, uv.w, acc[2][3]);
            acc[3][0] = fmaf(kw3, uv.x, acc[3][0]);
            acc[3][1] = fmaf(kw3, uv.y, acc[3][1]);
            acc[3][2] = fmaf(kw3, uv.z, acc[3][2]);
            acc[3][3] = fmaf(kw3, uv.w, acc[3][3]);
            kw3 = kw2; kw2 = kw1; kw1 = kw0;
            kw0 = kkp[CC - 1 + t0 - sg];
        }
    }
    // ---- store: ch = chgrp*4 + c -> b = chgrp, r = c (contiguous float4)
    #pragma unroll
    for (int t = 0; t < 4; t++) {
        float4 o = make_float4(acc[t][0], acc[t][1], acc[t][2], acc[t][3]);
        *(float4*)&y[((size_t)(chgrp * LL + j * CC + t0 + t)) * DD + h * NH] = o;
    }
}

// ---------------- launch ----------------
extern "C" void kernel_launch(void* const* d_in, const int* in_sizes, int n_in,
                              void* d_out, int out_size) {
    const float* u = (const float*)d_in[0];
    const float* a = (const float*)d_in[1];
    const float* b = (const float*)d_in[2];
    const float* c = (const float*)d_in[3];
    float* y = (float*)d_out;

    k_norm<<<NK, KD>>>(a);
    k_flag<<<1, NK>>>();
    k_precomp<<<NK, 256>>>(a, b, c);
    const int smg = (CC * KD + 4 * CC * NCH) * sizeof(float);  // 64 KB
    cudaFuncSetAttribute(k_g, cudaFuncAttributeMaxDynamicSharedMemorySize, smg);
    k_g<<<dim3(JJ / 4, NK), 256, smg>>>(u);
    k_scan<<<NK * 4, 64>>>();
    k_y<<<dim3(JJ, NK), 128>>>(u, y);
}

// round 4
// speedup vs baseline: 4.8539x; 1.3504x over previous
#include <cuda_runtime.h>
#include <cuda_bf16.h>
#include <cstdint>
#include <cstddef>

#define BB 4
#define LL 4096
#define DD 1024
#define NK 256
#define KD 64
#define NH 4
#define CC 128
#define JJ 32
#define NCH 16
#define NTOT 512       // JJ*NCH
#define XT 192         // CC + KD

// ---------------- device scratch ----------------
__device__ float g_anorm[NK];
__device__ int   g_flag;
__device__ __align__(16) float g_X [NK][XT][KD];
__device__ __align__(16) float g_Nt[NK][CC][KD];
__device__ __align__(16) float g_P [NK][KD][KD];
__device__ __align__(16) float g_G [NK][KD][NTOT];
__device__ __align__(256) __nv_bfloat16 g_Wh[NK][CC][XT];
__device__ __align__(256) __nv_bfloat16 g_Wl[NK][CC][XT];
__device__ __align__(256) __nv_bfloat16 g_Th[NK][KD][CC];
__device__ __align__(256) __nv_bfloat16 g_Tl[NK][KD][CC];
__device__ __align__(256) __nv_bfloat16 g_ubh[NK][NTOT][CC];
__device__ __align__(256) __nv_bfloat16 g_ubl[NK][NTOT][CC];
__device__ __align__(256) __nv_bfloat16 g_Hbh[NK][NTOT][KD];
__device__ __align__(256) __nv_bfloat16 g_Hbl[NK][NTOT][KD];

// ---------------- helpers ----------------
__device__ __forceinline__ uint32_t smem_u32(const void* p) {
    uint32_t a;
    asm("{ .reg .u64 t; cvta.to.shared.u64 t, %1; cvt.u32.u64 %0, t; }" : "=r"(a) : "l"(p));
    return a;
}
#define CP16(s, g) asm volatile("cp.async.cg.shared.global [%0], [%1], 16;" \
    :: "r"(s), "l"(__cvta_generic_to_global(g)))
#define CP_COMMIT() asm volatile("cp.async.commit_group;" ::: "memory")
#define CP_WAIT1()  asm volatile("cp.async.wait_group 1;" ::: "memory")
#define CP_WAIT0()  asm volatile("cp.async.wait_group 0;" ::: "memory")

#define MMA16816(c0, c1, c2, c3, a0, a1, a2, a3, b0, b1) \
    asm volatile("mma.sync.aligned.m16n8k16.row.col.f32.bf16.bf16.f32 " \
        "{%0,%1,%2,%3}, {%4,%5,%6,%7}, {%8,%9}, {%0,%1,%2,%3};" \
        : "+f"(c0), "+f"(c1), "+f"(c2), "+f"(c3) \
        : "r"(a0), "r"(a1), "r"(a2), "r"(a3), "r"(b0), "r"(b1))

#define ASTRIDE 72   // smem row stride in bf16 (conflict-free fragment LDS)

// ---------------- 1) per-head L1 norm ----------------
__global__ void k_norm(const float* __restrict__ a) {
    int h = blockIdx.x, i = threadIdx.x;
    float v = fabsf(a[h * KD + i]);
    #pragma unroll
    for (int o = 16; o; o >>= 1) v += __shfl_down_sync(0xffffffffu, v, o);
    __shared__ float sm[2];
    if ((i & 31) == 0) sm[i >> 5] = v;
    __syncthreads();
    if (i == 0) g_anorm[h] = sm[0] + sm[1];
}

// ---------------- 2) flag ----------------
__global__ void k_flag() {
    int t = threadIdx.x;
    float v = g_anorm[t];
    __shared__ float sm[8];
    #pragma unroll
    for (int o = 16; o; o >>= 1) v += __shfl_down_sync(0xffffffffu, v, o);
    if ((t & 31) == 0) sm[t >> 5] = v;
    __syncthreads();
    if (t == 0) {
        float s = 0.f;
        #pragma unroll
        for (int w = 0; w < 8; w++) s += sm[w];
        g_flag = (s / (float)NK > 1e-4f) ? 1 : 0;
    }
}

// ---------------- 3) precompute: trajectories -> W(hi/lo), T(hi/lo), P ----
__global__ __launch_bounds__(256) void k_precomp(const float* __restrict__ a,
                                                 const float* __restrict__ b,
                                                 const float* __restrict__ c) {
    int h = blockIdx.x, tid = threadIdx.x;
    __shared__ float an[KD], cs[KD], bs[KD], ss[XT], kk[CC];
    if (tid < KD) {
        float av = a[h * KD + tid];
        an[tid] = g_flag ? (av / g_anorm[h]) : av;
        cs[tid] = c[h * KD + tid];
        bs[tid] = b[h * KD + tid];
    }
    __syncthreads();
    int wid = tid >> 5, lane = tid & 31;
    if (wid == 0) {
        float x0 = (lane == 0) ? 1.f : 0.f, x1 = 0.f;
        float alo = an[lane], ahi = an[lane + 32];
        g_X[h][0][lane] = x0; g_X[h][0][lane + 32] = x1;
        for (int t = 1; t < XT; t++) {
            float last = __shfl_sync(0xffffffffu, x1, 31);
            float top  = __shfl_sync(0xffffffffu, x0, 31);
            float sx0  = __shfl_up_sync(0xffffffffu, x0, 1);
            float sx1  = __shfl_up_sync(0xffffffffu, x1, 1);
            if (lane == 0) { sx0 = 0.f; sx1 = top; }
            x0 = fmaf(alo, last, sx0);
            x1 = fmaf(ahi, last, sx1);
            g_X[h][t][lane] = x0; g_X[h][t][lane + 32] = x1;
        }
    } else if (wid == 1) {
        float x0 = bs[lane], x1 = bs[lane + 32];
        float alo = an[lane], ahi = an[lane + 32];
        g_Nt[h][CC - 1][lane] = x0; g_Nt[h][CC - 1][lane + 32] = x1;
        for (int t = 1; t < CC; t++) {
            float last = __shfl_sync(0xffffffffu, x1, 31);
            float top  = __shfl_sync(0xffffffffu, x0, 31);
            float sx0  = __shfl_up_sync(0xffffffffu, x0, 1);
            float sx1  = __shfl_up_sync(0xffffffffu, x1, 1);
            if (lane == 0) { sx0 = 0.f; sx1 = top; }
            x0 = fmaf(alo, last, sx0);
            x1 = fmaf(ahi, last, sx1);
            g_Nt[h][CC - 1 - t][lane] = x0; g_Nt[h][CC - 1 - t][lane + 32] = x1;
        }
    }
    __syncthreads();
    if (tid >= 1 && tid < XT) {
        float acc = 0.f;
        #pragma unroll 16
        for (int i = 0; i < KD; i++) acc = fmaf(cs[i], g_X[h][tid][i], acc);
        ss[tid] = acc;
    }
    if (tid == 0) ss[0] = 0.f;
    if (tid < CC) {
        float acc = 0.f;
        #pragma unroll 16
        for (int i = 0; i < KD; i++) acc = fmaf(cs[i], g_Nt[h][CC - 1 - tid][i], acc);
        kk[tid] = acc;
    }
    for (int idx = tid; idx < KD * KD; idx += 256) {
        int i2 = idx >> 6, j2 = idx & 63;
        g_P[h][i2][j2] = g_X[h][CC + j2][i2];
    }
    __syncthreads();
    // W[tau][kq] : kq<128 -> Toeplitz(k), kq>=128 -> Hankel(s)
    for (int idx = tid; idx < CC * XT; idx += 256) {
        int tau = idx / XT, kq = idx % XT;
        float v;
        if (kq < CC) v = (kq <= tau) ? kk[tau - kq] : 0.f;
        else         v = ss[tau + 1 + (kq - CC)];
        __nv_bfloat16 hi = __float2bfloat16(v);
        __nv_bfloat16 lo = __float2bfloat16(v - __bfloat162float(hi));
        g_Wh[h][tau][kq] = hi;
        g_Wl[h][tau][kq] = lo;
    }
    // T[i][sigma] = Nt[sigma][i]
    for (int idx = tid; idx < KD * CC; idx += 256) {
        int i2 = idx >> 7, sg = idx & 127;
        float v = g_Nt[h][sg][i2];
        __nv_bfloat16 hi = __float2bfloat16(v);
        __nv_bfloat16 lo = __float2bfloat16(v - __bfloat162float(hi));
        g_Th[h][i2][sg] = hi;
        g_Tl[h][i2][sg] = lo;
    }
}

// ---------------- 4) transpose u -> ub hi/lo (bf16, time-contiguous) ----
__global__ __launch_bounds__(256) void k_tr(const float* __restrict__ u) {
    __shared__ float ts[CC][65];
    int bid = blockIdx.x;
    int dblk = bid & 15, b = (bid >> 4) & 3, j = bid >> 6;
    int tid = threadIdx.x;
    #pragma unroll
    for (int it = 0; it < 8; it++) {
        int idx = tid + 256 * it;            // 2048 float4
        int sg = idx >> 4, dq = idx & 15;
        float4 v = *(const float4*)&u[((size_t)(b * LL + j * CC + sg)) * DD + dblk * 64 + dq * 4];
        ts[sg][dq * 4 + 0] = v.x; ts[sg][dq * 4 + 1] = v.y;
        ts[sg][dq * 4 + 2] = v.z; ts[sg][dq * 4 + 3] = v.w;
    }
    __syncthreads();
    int row = tid >> 2, part = tid & 3;      // row = local d, part = sigma quarter
    int dg = dblk * 64 + row;
    int h = dg >> 2, r = dg & 3;
    int n = j * NCH + b * 4 + r;
    uint32_t hv[16], lv[16];
    #pragma unroll
    for (int t = 0; t < 32; t += 2) {
        float f0 = ts[part * 32 + t][row];
        float f1 = ts[part * 32 + t + 1][row];
        __nv_bfloat16 h0 = __float2bfloat16(f0);
        __nv_bfloat16 h1 = __float2bfloat16(f1);
        __nv_bfloat16 l0 = __float2bfloat16(f0 - __bfloat162float(h0));
        __nv_bfloat16 l1 = __float2bfloat16(f1 - __bfloat162float(h1));
        hv[t >> 1] = (uint32_t)__bfloat16_as_ushort(h0) | ((uint32_t)__bfloat16_as_ushort(h1) << 16);
        lv[t >> 1] = (uint32_t)__bfloat16_as_ushort(l0) | ((uint32_t)__bfloat16_as_ushort(l1) << 16);
    }
    uint4* dh = (uint4*)&g_ubh[h][n][part * 32];
    uint4* dl = (uint4*)&g_ubl[h][n][part * 32];
    #pragma unroll
    for (int q = 0; q < 4; q++) {
        dh[q] = make_uint4(hv[q * 4], hv[q * 4 + 1], hv[q * 4 + 2], hv[q * 4 + 3]);
        dl[q] = make_uint4(lv[q * 4], lv[q * 4 + 1], lv[q * 4 + 2], lv[q * 4 + 3]);
    }
}

// ================ GEMM-A: G[64,512] = T @ ub^T (3 hi/lo terms) ==========
#define GA_AROWS 64
#define GA_AELE  (GA_AROWS * ASTRIDE)
#define GA_ABYTES (GA_AELE * 2)
#define GA_BELE  (128 * ASTRIDE)
#define GA_STG   (GA_ABYTES + GA_BELE * 2)
#define GA_SMEM  (2 * GA_STG)

__global__ __launch_bounds__(128) void k_gemm_g() {
    extern __shared__ char dsm[];
    int q = blockIdx.x, h = blockIdx.y, tid = threadIdx.x;
    int wid = tid >> 5, lane = tid & 31;
    int n0 = q * 128;
    int warpM = wid & 1, warpN = wid >> 1;
    int m0 = warpM * 32, nw0 = warpN * 64;
    int tg = lane >> 2, tq = lane & 3;
    uint32_t sbase = smem_u32(dsm);

    float acc[2][8][4];
    #pragma unroll
    for (int mf = 0; mf < 2; mf++)
        #pragma unroll
        for (int nf = 0; nf < 8; nf++)
            #pragma unroll
            for (int v = 0; v < 4; v++) acc[mf][nf][v] = 0.f;

    const int NC = 6;
    // chunk loader
    #define GA_LOAD(c) do { \
        int st_ = (c) & 1; \
        uint32_t sA = sbase + st_ * GA_STG; \
        uint32_t sB = sA + GA_ABYTES; \
        int kc = ((c) & 1) * 64; \
        const __nv_bfloat16* asrc = ((c) >= 4) ? &g_Tl[h][0][kc] : &g_Th[h][0][kc]; \
        const __nv_bfloat16* bsrc = ((c) == 2 || (c) == 3) ? &g_ubl[h][n0][kc] : &g_ubh[h][n0][kc]; \
        _Pragma("unroll") \
        for (int it = 0; it < 4; it++) { \
            int idx = tid + 128 * it; \
            int row = idx >> 3, cu = idx & 7; \
            CP16(sA + row * (ASTRIDE * 2) + cu * 16, (const char*)asrc + row * 256 + cu * 16); \
        } \
        _Pragma("unroll") \
        for (int it = 0; it < 8; it++) { \
            int idx = tid + 128 * it; \
            int row = idx >> 3, cu = idx & 7; \
            CP16(sB + row * (ASTRIDE * 2) + cu * 16, (const char*)bsrc + row * 256 + cu * 16); \
        } \
        CP_COMMIT(); \
    } while (0)

    GA_LOAD(0);
    #pragma unroll 1
    for (int c = 0; c < NC; c++) {
        if (c + 1 < NC) { GA_LOAD(c + 1); CP_WAIT1(); }
        else            { CP_WAIT0(); }
        __syncthreads();
        const __nv_bfloat16* As = (const __nv_bfloat16*)(dsm + (c & 1) * GA_STG);
        const __nv_bfloat16* Bs = As + GA_AELE;
        #pragma unroll
        for (int ks = 0; ks < 4; ks++) {
            int kk = ks * 16 + tq * 2;
            uint32_t afr[2][4];
            #pragma unroll
            for (int mf = 0; mf < 2; mf++) {
                int r0 = m0 + mf * 16 + tg;
                afr[mf][0] = *(const uint32_t*)(As + r0 * ASTRIDE + kk);
                afr[mf][1] = *(const uint32_t*)(As + (r0 + 8) * ASTRIDE + kk);
                afr[mf][2] = *(const uint32_t*)(As + r0 * ASTRIDE + kk + 8);
                afr[mf][3] = *(const uint32_t*)(As + (r0 + 8) * ASTRIDE + kk + 8);
            }
            #pragma unroll
            for (int nf = 0; nf < 8; nf++) {
                int cn = nw0 + nf * 8 + tg;
                uint32_t b0 = *(const uint32_t*)(Bs + cn * ASTRIDE + kk);
                uint32_t b1 = *(const uint32_t*)(Bs + cn * ASTRIDE + kk + 8);
                #pragma unroll
                for (int mf = 0; mf < 2; mf++)
                    MMA16816(acc[mf][nf][0], acc[mf][nf][1], acc[mf][nf][2], acc[mf][nf][3],
                             afr[mf][0], afr[mf][1], afr[mf][2], afr[mf][3], b0, b1);
            }
        }
        __syncthreads();
    }
    #undef GA_LOAD
    // epilogue -> g_G (fp32)
    #pragma unroll
    for (int mf = 0; mf < 2; mf++) {
        int i = m0 + mf * 16 + tg;
        #pragma unroll
        for (int nf = 0; nf < 8; nf++) {
            int n = n0 + nw0 + nf * 8 + tq * 2;
            *(float2*)&g_G[h][i][n]     = make_float2(acc[mf][nf][0], acc[mf][nf][1]);
            *(float2*)&g_G[h][i + 8][n] = make_float2(acc[mf][nf][2], acc[mf][nf][3]);
        }
    }
}

// ---------------- scan: H_j = P H_{j-1} + G_j ; emit H hi/lo ----------
__global__ __launch_bounds__(64) void k_scan() {
    int h = blockIdx.x >> 2, cq = blockIdx.x & 3, i = threadIdx.x;
    float P[KD];
    #pragma unroll
    for (int kq = 0; kq < KD; kq += 4) {
        float4 p = *(const float4*)&g_P[h][i][kq];
        P[kq] = p.x; P[kq + 1] = p.y; P[kq + 2] = p.z; P[kq + 3] = p.w;
    }
    __shared__ float hs[KD][4];
    float hv[4] = {0.f, 0.f, 0.f, 0.f};
    for (int j = 0; j < JJ; j++) {
        #pragma unroll
        for (int cch = 0; cch < 4; cch++) {
            int n = j * NCH + cq * 4 + cch;
            __nv_bfloat16 hi = __float2bfloat16(hv[cch]);
            g_Hbh[h][n][i] = hi;
            g_Hbl[h][n][i] = __float2bfloat16(hv[cch] - __bfloat162float(hi));
        }
        *(float4*)&hs[i][0] = make_float4(hv[0], hv[1], hv[2], hv[3]);
        __syncthreads();
        float4 g = *(const float4*)&g_G[h][i][j * NCH + cq * 4];
        float acc[4] = {g.x, g.y, g.z, g.w};
        #pragma unroll
        for (int kq = 0; kq < KD; kq++) {
            float4 hk = *(const float4*)&hs[kq][0];
            acc[0] = fmaf(P[kq], hk.x, acc[0]);
            acc[1] = fmaf(P[kq], hk.y, acc[1]);
            acc[2] = fmaf(P[kq], hk.z, acc[2]);
            acc[3] = fmaf(P[kq], hk.w, acc[3]);
        }
        __syncthreads();
        hv[0] = acc[0]; hv[1] = acc[1]; hv[2] = acc[2]; hv[3] = acc[3];
    }
}

// ============ GEMM-B: Y[128,512] = [Toep|Hank] @ [u|H]^T, write y =======
#define GB_AELE  (128 * ASTRIDE)
#define GB_ABYTES (GB_AELE * 2)
#define GB_STG   (2 * GB_ABYTES)
#define GB_SMEM  (2 * GB_STG)

__global__ __launch_bounds__(256) void k_gemm_y(float* __restrict__ y) {
    extern __shared__ char dsm[];
    int q = blockIdx.x, h = blockIdx.y, tid = threadIdx.x;
    int wid = tid >> 5, lane = tid & 31;
    int n0 = q * 128;
    int warpM = wid & 3, warpN = wid >> 2;
    int m0 = warpM * 32, nw0 = warpN * 64;
    int tg = lane >> 2, tq = lane & 3;
    uint32_t sbase = smem_u32(dsm);

    float acc[2][8][4];
    #pragma unroll
    for (int mf = 0; mf < 2; mf++)
        #pragma unroll
        for (int nf = 0; nf < 8; nf++)
            #pragma unroll
            for (int v = 0; v < 4; v++) acc[mf][nf][v] = 0.f;

    const int NC = 9;
    #define GB_LOAD(c) do { \
        int st_ = (c) & 1; \
        uint32_t sA = sbase + st_ * GB_STG; \
        uint32_t sB = sA + GB_ABYTES; \
        int seg = (c) / 3, kc3 = (c) % 3; \
        const __nv_bfloat16* asrc = (seg == 1) ? &g_Wl[h][0][kc3 * 64] : &g_Wh[h][0][kc3 * 64]; \
        const __nv_bfloat16* bsrc; int brs; \
        if (kc3 < 2) { bsrc = (seg < 2) ? &g_ubh[h][n0][kc3 * 64] : &g_ubl[h][n0][kc3 * 64]; brs = 256; } \
        else         { bsrc = (seg < 2) ? &g_Hbh[h][n0][0] : &g_Hbl[h][n0][0]; brs = 128; } \
        _Pragma("unroll") \
        for (int it = 0; it < 4; it++) { \
            int idx = tid + 256 * it; \
            int row = idx >> 3, cu = idx & 7; \
            CP16(sA + row * (ASTRIDE * 2) + cu * 16, (const char*)asrc + row * 384 + cu * 16); \
        } \
        _Pragma("unroll") \
        for (int it = 0; it < 4; it++) { \
            int idx = tid + 256 * it; \
            int row = idx >> 3, cu = idx & 7; \
            CP16(sB + row * (ASTRIDE * 2) + cu * 16, (const char*)bsrc + row * brs + cu * 16); \
        } \
        CP_COMMIT(); \
    } while (0)

    GB_LOAD(0);
    #pragma unroll 1
    for (int c = 0; c < NC; c++) {
        if (c + 1 < NC) { GB_LOAD(c + 1); CP_WAIT1(); }
        else            { CP_WAIT0(); }
        __syncthreads();
        const __nv_bfloat16* As = (const __nv_bfloat16*)(dsm + (c & 1) * GB_STG);
        const __nv_bfloat16* Bs = As + GB_AELE;
        #pragma unroll
        for (int ks = 0; ks < 4; ks++) {
            int kk = ks * 16 + tq * 2;
            uint32_t afr[2][4];
            #pragma unroll
            for (int mf = 0; mf < 2; mf++) {
                int r0 = m0 + mf * 16 + tg;
                afr[mf][0] = *(const uint32_t*)(As + r0 * ASTRIDE + kk);
                afr[mf][1] = *(const uint32_t*)(As + (r0 + 8) * ASTRIDE + kk);
                afr[mf][2] = *(const uint32_t*)(As + r0 * ASTRIDE + kk + 8);
                afr[mf][3] = *(const uint32_t*)(As + (r0 + 8) * ASTRIDE + kk + 8);
            }
            #pragma unroll
            for (int nf = 0; nf < 8; nf++) {
                int cn = nw0 + nf * 8 + tg;
                uint32_t b0 = *(const uint32_t*)(Bs + cn * ASTRIDE + kk);
                uint32_t b1 = *(const uint32_t*)(Bs + cn * ASTRIDE + kk + 8);
                #pragma unroll
                for (int mf = 0; mf < 2; mf++)
                    MMA16816(acc[mf][nf][0], acc[mf][nf][1], acc[mf][nf][2], acc[mf][nf][3],
                             afr[mf][0], afr[mf][1], afr[mf][2], afr[mf][3], b0, b1);
            }
        }
        __syncthreads();
    }
    #undef GB_LOAD
    // epilogue -> y
    #pragma unroll
    for (int mf = 0; mf < 2; mf++) {
        int tau = m0 + mf * 16 + tg;
        #pragma unroll
        for (int nf = 0; nf < 8; nf++) {
            int n = n0 + nw0 + nf * 8 + tq * 2;
            int j = n >> 4, b = (n >> 2) & 3, r = n & 3;
            size_t base = ((size_t)(b * LL + j * CC + tau)) * DD + h * NH + r;
            *(float2*)&y[base]            = make_float2(acc[mf][nf][0], acc[mf][nf][1]);
            *(float2*)&y[base + 8 * DD]   = make_float2(acc[mf][nf][2], acc[mf][nf][3]);
        }
    }
}

// ---------------- launch ----------------
extern "C" void kernel_launch(void* const* d_in, const int* in_sizes, int n_in,
                              void* d_out, int out_size) {
    const float* u = (const float*)d_in[0];
    const float* a = (const float*)d_in[1];
    const float* b = (const float*)d_in[2];
    const float* c = (const float*)d_in[3];
    float* y = (float*)d_out;

    cudaFuncSetAttribute(k_gemm_g, cudaFuncAttributeMaxDynamicSharedMemorySize, GA_SMEM);
    cudaFuncSetAttribute(k_gemm_y, cudaFuncAttributeMaxDynamicSharedMemorySize, GB_SMEM);

    k_norm<<<NK, KD>>>(a);
    k_flag<<<1, NK>>>();
    k_precomp<<<NK, 256>>>(a, b, c);
    k_tr<<<2048, 256>>>(u);
    k_gemm_g<<<dim3(4, NK), 128, GA_SMEM>>>();
    k_scan<<<NK * 4, 64>>>();
    k_gemm_y<<<dim3(4, NK), 256, GB_SMEM>>>(y);
}

// round 5
// speedup vs baseline: 5.0274x; 1.0358x over previous
#include <cuda_runtime.h>
#include <cuda_bf16.h>
#include <cstdint>
#include <cstddef>

#define BB 4
#define LL 4096
#define DD 1024
#define NK 256
#define KD 64
#define NH 4
#define CC 128
#define JJ 32
#define NCH 16
#define NTOT 512       // JJ*NCH
#define XT 192         // CC + KD

// ---------------- device scratch ----------------
__device__ float g_anorm[NK];
__device__ int   g_flag;
__device__ __align__(16) float g_X [NK][XT][KD];
__device__ __align__(16) float g_Nt[NK][CC][KD];
__device__ __align__(16) float g_P [NK][KD][KD];
__device__ __align__(16) float g_G [NK][KD][NTOT];
__device__ __align__(256) __nv_bfloat16 g_Wh[NK][CC][XT];
__device__ __align__(256) __nv_bfloat16 g_Wl[NK][CC][XT];
__device__ __align__(256) __nv_bfloat16 g_Th[NK][KD][CC];
__device__ __align__(256) __nv_bfloat16 g_Tl[NK][KD][CC];
__device__ __align__(256) __nv_bfloat16 g_ubh[NK][NTOT][CC];
__device__ __align__(256) __nv_bfloat16 g_ubl[NK][NTOT][CC];
__device__ __align__(256) __nv_bfloat16 g_Hbh[NK][NTOT][KD];
__device__ __align__(256) __nv_bfloat16 g_Hbl[NK][NTOT][KD];

// ---------------- helpers ----------------
__device__ __forceinline__ uint32_t smem_u32(const void* p) {
    uint32_t a;
    asm("{ .reg .u64 t; cvta.to.shared.u64 t, %1; cvt.u32.u64 %0, t; }" : "=r"(a) : "l"(p));
    return a;
}
#define CP16(s, g) asm volatile("cp.async.cg.shared.global [%0], [%1], 16;" \
    :: "r"(s), "l"(__cvta_generic_to_global(g)))
#define CP_COMMIT() asm volatile("cp.async.commit_group;" ::: "memory")
#define CP_WAIT1()  asm volatile("cp.async.wait_group 1;" ::: "memory")
#define CP_WAIT0()  asm volatile("cp.async.wait_group 0;" ::: "memory")

#define MMA16816(c0, c1, c2, c3, a0, a1, a2, a3, b0, b1) \
    asm volatile("mma.sync.aligned.m16n8k16.row.col.f32.bf16.bf16.f32 " \
        "{%0,%1,%2,%3}, {%4,%5,%6,%7}, {%8,%9}, {%0,%1,%2,%3};" \
        : "+f"(c0), "+f"(c1), "+f"(c2), "+f"(c3) \
        : "r"(a0), "r"(a1), "r"(a2), "r"(a3), "r"(b0), "r"(b1))

#define LDSM4(r, addr) \
    asm volatile("ldmatrix.sync.aligned.m8n8.x4.shared.b16 {%0,%1,%2,%3}, [%4];" \
        : "=r"((r)[0]), "=r"((r)[1]), "=r"((r)[2]), "=r"((r)[3]) : "r"(addr))

#define ASTRIDE 72   // smem row stride in bf16 (conflict-free LDSM phases)

// ---------------- 1) per-head L1 norm ----------------
__global__ void k_norm(const float* __restrict__ a) {
    int h = blockIdx.x, i = threadIdx.x;
    float v = fabsf(a[h * KD + i]);
    #pragma unroll
    for (int o = 16; o; o >>= 1) v += __shfl_down_sync(0xffffffffu, v, o);
    __shared__ float sm[2];
    if ((i & 31) == 0) sm[i >> 5] = v;
    __syncthreads();
    if (i == 0) g_anorm[h] = sm[0] + sm[1];
}

// ---------------- 2) flag ----------------
__global__ void k_flag() {
    int t = threadIdx.x;
    float v = g_anorm[t];
    __shared__ float sm[8];
    #pragma unroll
    for (int o = 16; o; o >>= 1) v += __shfl_down_sync(0xffffffffu, v, o);
    if ((t & 31) == 0) sm[t >> 5] = v;
    __syncthreads();
    if (t == 0) {
        float s = 0.f;
        #pragma unroll
        for (int w = 0; w < 8; w++) s += sm[w];
        g_flag = (s / (float)NK > 1e-4f) ? 1 : 0;
    }
}

// ---------------- 3) precompute: trajectories -> W(hi/lo), T(hi/lo), P ----
__global__ __launch_bounds__(256) void k_precomp(const float* __restrict__ a,
                                                 const float* __restrict__ b,
                                                 const float* __restrict__ c) {
    int h = blockIdx.x, tid = threadIdx.x;
    __shared__ float an[KD], cs[KD], bs[KD], ss[XT], kk[CC];
    if (tid < KD) {
        float av = a[h * KD + tid];
        an[tid] = g_flag ? (av / g_anorm[h]) : av;
        cs[tid] = c[h * KD + tid];
        bs[tid] = b[h * KD + tid];
    }
    __syncthreads();
    int wid = tid >> 5, lane = tid & 31;
    if (wid == 0) {
        float x0 = (lane == 0) ? 1.f : 0.f, x1 = 0.f;
        float alo = an[lane], ahi = an[lane + 32];
        g_X[h][0][lane] = x0; g_X[h][0][lane + 32] = x1;
        for (int t = 1; t < XT; t++) {
            float last = __shfl_sync(0xffffffffu, x1, 31);
            float top  = __shfl_sync(0xffffffffu, x0, 31);
            float sx0  = __shfl_up_sync(0xffffffffu, x0, 1);
            float sx1  = __shfl_up_sync(0xffffffffu, x1, 1);
            if (lane == 0) { sx0 = 0.f; sx1 = top; }
            x0 = fmaf(alo, last, sx0);
            x1 = fmaf(ahi, last, sx1);
            g_X[h][t][lane] = x0; g_X[h][t][lane + 32] = x1;
        }
    } else if (wid == 1) {
        float x0 = bs[lane], x1 = bs[lane + 32];
        float alo = an[lane], ahi = an[lane + 32];
        g_Nt[h][CC - 1][lane] = x0; g_Nt[h][CC - 1][lane + 32] = x1;
        for (int t = 1; t < CC; t++) {
            float last = __shfl_sync(0xffffffffu, x1, 31);
            float top  = __shfl_sync(0xffffffffu, x0, 31);
            float sx0  = __shfl_up_sync(0xffffffffu, x0, 1);
            float sx1  = __shfl_up_sync(0xffffffffu, x1, 1);
            if (lane == 0) { sx0 = 0.f; sx1 = top; }
            x0 = fmaf(alo, last, sx0);
            x1 = fmaf(ahi, last, sx1);
            g_Nt[h][CC - 1 - t][lane] = x0; g_Nt[h][CC - 1 - t][lane + 32] = x1;
        }
    }
    __syncthreads();
    if (tid >= 1 && tid < XT) {
        float acc = 0.f;
        #pragma unroll 16
        for (int i = 0; i < KD; i++) acc = fmaf(cs[i], g_X[h][tid][i], acc);
        ss[tid] = acc;
    }
    if (tid == 0) ss[0] = 0.f;
    if (tid < CC) {
        float acc = 0.f;
        #pragma unroll 16
        for (int i = 0; i < KD; i++) acc = fmaf(cs[i], g_Nt[h][CC - 1 - tid][i], acc);
        kk[tid] = acc;
    }
    for (int idx = tid; idx < KD * KD; idx += 256) {
        int i2 = idx >> 6, j2 = idx & 63;
        g_P[h][i2][j2] = g_X[h][CC + j2][i2];
    }
    __syncthreads();
    // W[tau][kq] : kq<128 -> Toeplitz(k), kq>=128 -> Hankel(s)
    for (int idx = tid; idx < CC * XT; idx += 256) {
        int tau = idx / XT, kq = idx % XT;
        float v;
        if (kq < CC) v = (kq <= tau) ? kk[tau - kq] : 0.f;
        else         v = ss[tau + 1 + (kq - CC)];
        __nv_bfloat16 hi = __float2bfloat16(v);
        __nv_bfloat16 lo = __float2bfloat16(v - __bfloat162float(hi));
        g_Wh[h][tau][kq] = hi;
        g_Wl[h][tau][kq] = lo;
    }
    // T[i][sigma] = Nt[sigma][i]
    for (int idx = tid; idx < KD * CC; idx += 256) {
        int i2 = idx >> 7, sg = idx & 127;
        float v = g_Nt[h][sg][i2];
        __nv_bfloat16 hi = __float2bfloat16(v);
        __nv_bfloat16 lo = __float2bfloat16(v - __bfloat162float(hi));
        g_Th[h][i2][sg] = hi;
        g_Tl[h][i2][sg] = lo;
    }
}

// ---------------- 4) transpose u -> ub hi/lo (bf16, time-contiguous) ----
__global__ __launch_bounds__(256) void k_tr(const float* __restrict__ u) {
    __shared__ float ts[CC][65];
    int bid = blockIdx.x;
    int dblk = bid & 15, b = (bid >> 4) & 3, j = bid >> 6;
    int tid = threadIdx.x;
    #pragma unroll
    for (int it = 0; it < 8; it++) {
        int idx = tid + 256 * it;            // 2048 float4
        int sg = idx >> 4, dq = idx & 15;
        float4 v = *(const float4*)&u[((size_t)(b * LL + j * CC + sg)) * DD + dblk * 64 + dq * 4];
        ts[sg][dq * 4 + 0] = v.x; ts[sg][dq * 4 + 1] = v.y;
        ts[sg][dq * 4 + 2] = v.z; ts[sg][dq * 4 + 3] = v.w;
    }
    __syncthreads();
    int row = tid >> 2, part = tid & 3;      // row = local d, part = sigma quarter
    int dg = dblk * 64 + row;
    int h = dg >> 2, r = dg & 3;
    int n = j * NCH + b * 4 + r;
    uint32_t hv[16], lv[16];
    #pragma unroll
    for (int t = 0; t < 32; t += 2) {
        float f0 = ts[part * 32 + t][row];
        float f1 = ts[part * 32 + t + 1][row];
        __nv_bfloat16 h0 = __float2bfloat16(f0);
        __nv_bfloat16 h1 = __float2bfloat16(f1);
        __nv_bfloat16 l0 = __float2bfloat16(f0 - __bfloat162float(h0));
        __nv_bfloat16 l1 = __float2bfloat16(f1 - __bfloat162float(h1));
        hv[t >> 1] = (uint32_t)__bfloat16_as_ushort(h0) | ((uint32_t)__bfloat16_as_ushort(h1) << 16);
        lv[t >> 1] = (uint32_t)__bfloat16_as_ushort(l0) | ((uint32_t)__bfloat16_as_ushort(l1) << 16);
    }
    uint4* dh = (uint4*)&g_ubh[h][n][part * 32];
    uint4* dl = (uint4*)&g_ubl[h][n][part * 32];
    #pragma unroll
    for (int q = 0; q < 4; q++) {
        dh[q] = make_uint4(hv[q * 4], hv[q * 4 + 1], hv[q * 4 + 2], hv[q * 4 + 3]);
        dl[q] = make_uint4(lv[q * 4], lv[q * 4 + 1], lv[q * 4 + 2], lv[q * 4 + 3]);
    }
}

// ================ GEMM-A: G[64,512] = T @ ub^T (3 hi/lo terms) ==========
#define GA_AROWS 64
#define GA_AELE  (GA_AROWS * ASTRIDE)
#define GA_ABYTES (GA_AELE * 2)
#define GA_BELE  (128 * ASTRIDE)
#define GA_STG   (GA_ABYTES + GA_BELE * 2)
#define GA_SMEM  (2 * GA_STG)

__global__ __launch_bounds__(128) void k_gemm_g() {
    extern __shared__ char dsm[];
    int q = blockIdx.x, h = blockIdx.y, tid = threadIdx.x;
    int wid = tid >> 5, lane = tid & 31;
    int n0 = q * 128;
    int warpM = wid & 1, warpN = wid >> 1;
    int m0 = warpM * 32, nw0 = warpN * 64;
    int tg = lane >> 2, tq = lane & 3;
    uint32_t sbase = smem_u32(dsm);
    // ldmatrix in-tile byte offsets
    uint32_t aOff = (uint32_t)(((m0 + (lane & 15)) * ASTRIDE + (lane >> 4) * 8) * 2);
    uint32_t bOff = (uint32_t)(((nw0 + (lane & 7) + ((lane >> 4) & 1) * 8) * ASTRIDE
                                + ((lane >> 3) & 1) * 8) * 2);

    float acc[2][8][4];
    #pragma unroll
    for (int mf = 0; mf < 2; mf++)
        #pragma unroll
        for (int nf = 0; nf < 8; nf++)
            #pragma unroll
            for (int v = 0; v < 4; v++) acc[mf][nf][v] = 0.f;

    const int NC = 6;
    #define GA_LOAD(c) do { \
        int st_ = (c) & 1; \
        uint32_t sA = sbase + st_ * GA_STG; \
        uint32_t sB = sA + GA_ABYTES; \
        int kc = ((c) & 1) * 64; \
        const __nv_bfloat16* asrc = ((c) >= 4) ? &g_Tl[h][0][kc] : &g_Th[h][0][kc]; \
        const __nv_bfloat16* bsrc = ((c) == 2 || (c) == 3) ? &g_ubl[h][n0][kc] : &g_ubh[h][n0][kc]; \
        _Pragma("unroll") \
        for (int it = 0; it < 4; it++) { \
            int idx = tid + 128 * it; \
            int row = idx >> 3, cu = idx & 7; \
            CP16(sA + row * (ASTRIDE * 2) + cu * 16, (const char*)asrc + row * 256 + cu * 16); \
        } \
        _Pragma("unroll") \
        for (int it = 0; it < 8; it++) { \
            int idx = tid + 128 * it; \
            int row = idx >> 3, cu = idx & 7; \
            CP16(sB + row * (ASTRIDE * 2) + cu * 16, (const char*)bsrc + row * 256 + cu * 16); \
        } \
        CP_COMMIT(); \
    } while (0)

    GA_LOAD(0);
    #pragma unroll 1
    for (int c = 0; c < NC; c++) {
        if (c + 1 < NC) { GA_LOAD(c + 1); CP_WAIT1(); }
        else            { CP_WAIT0(); }
        __syncthreads();
        uint32_t sA = sbase + (c & 1) * GA_STG;
        uint32_t sB = sA + GA_ABYTES;
        uint32_t aAddr = sA + aOff;
        uint32_t bAddr = sB + bOff;
        #pragma unroll
        for (int ks = 0; ks < 4; ks++) {
            uint32_t afr[2][4];
            LDSM4(afr[0], aAddr + ks * 32);
            LDSM4(afr[1], aAddr + 16 * ASTRIDE * 2 + ks * 32);
            uint32_t bfr[4][4];
            #pragma unroll
            for (int p = 0; p < 4; p++)
                LDSM4(bfr[p], bAddr + p * 16 * ASTRIDE * 2 + ks * 32);
            #pragma unroll
            for (int p = 0; p < 4; p++)
                #pragma unroll
                for (int sub = 0; sub < 2; sub++) {
                    int nf = p * 2 + sub;
                    uint32_t b0 = bfr[p][sub * 2], b1 = bfr[p][sub * 2 + 1];
                    #pragma unroll
                    for (int mf = 0; mf < 2; mf++)
                        MMA16816(acc[mf][nf][0], acc[mf][nf][1], acc[mf][nf][2], acc[mf][nf][3],
                                 afr[mf][0], afr[mf][1], afr[mf][2], afr[mf][3], b0, b1);
                }
        }
        __syncthreads();
    }
    #undef GA_LOAD
    // epilogue -> g_G (fp32)
    #pragma unroll
    for (int mf = 0; mf < 2; mf++) {
        int i = m0 + mf * 16 + tg;
        #pragma unroll
        for (int nf = 0; nf < 8; nf++) {
            int n = n0 + nw0 + nf * 8 + tq * 2;
            *(float2*)&g_G[h][i][n]     = make_float2(acc[mf][nf][0], acc[mf][nf][1]);
            *(float2*)&g_G[h][i + 8][n] = make_float2(acc[mf][nf][2], acc[mf][nf][3]);
        }
    }
}

// ---------------- scan: H_j = P H_{j-1} + G_j ; emit H hi/lo ----------
__global__ __launch_bounds__(64) void k_scan() {
    int h = blockIdx.x >> 2, cq = blockIdx.x & 3, i = threadIdx.x;
    float P[KD];
    #pragma unroll
    for (int kq = 0; kq < KD; kq += 4) {
        float4 p = *(const float4*)&g_P[h][i][kq];
        P[kq] = p.x; P[kq + 1] = p.y; P[kq + 2] = p.z; P[kq + 3] = p.w;
    }
    __shared__ float hs[KD][4];
    float hv[4] = {0.f, 0.f, 0.f, 0.f};
    for (int j = 0; j < JJ; j++) {
        #pragma unroll
        for (int cch = 0; cch < 4; cch++) {
            int n = j * NCH + cq * 4 + cch;
            __nv_bfloat16 hi = __float2bfloat16(hv[cch]);
            g_Hbh[h][n][i] = hi;
            g_Hbl[h][n][i] = __float2bfloat16(hv[cch] - __bfloat162float(hi));
        }
        *(float4*)&hs[i][0] = make_float4(hv[0], hv[1], hv[2], hv[3]);
        __syncthreads();
        float4 g = *(const float4*)&g_G[h][i][j * NCH + cq * 4];
        float acc[4] = {g.x, g.y, g.z, g.w};
        #pragma unroll
        for (int kq = 0; kq < KD; kq++) {
            float4 hk = *(const float4*)&hs[kq][0];
            acc[0] = fmaf(P[kq], hk.x, acc[0]);
            acc[1] = fmaf(P[kq], hk.y, acc[1]);
            acc[2] = fmaf(P[kq], hk.z, acc[2]);
            acc[3] = fmaf(P[kq], hk.w, acc[3]);
        }
        __syncthreads();
        hv[0] = acc[0]; hv[1] = acc[1]; hv[2] = acc[2]; hv[3] = acc[3];
    }
}

// ============ GEMM-B: Y[128,512] = [Toep|Hank] @ [u|H]^T, write y =======
#define GB_AELE  (128 * ASTRIDE)
#define GB_ABYTES (GB_AELE * 2)
#define GB_STG   (2 * GB_ABYTES)
#define GB_SMEM  (2 * GB_STG)

__global__ __launch_bounds__(256) void k_gemm_y(float* __restrict__ y) {
    extern __shared__ char dsm[];
    int q = blockIdx.x, h = blockIdx.y, tid = threadIdx.x;
    int wid = tid >> 5, lane = tid & 31;
    int n0 = q * 128;
    int warpM = wid & 3, warpN = wid >> 2;
    int m0 = warpM * 32, nw0 = warpN * 64;
    int tg = lane >> 2, tq = lane & 3;
    uint32_t sbase = smem_u32(dsm);
    uint32_t aOff = (uint32_t)(((m0 + (lane & 15)) * ASTRIDE + (lane >> 4) * 8) * 2);
    uint32_t bOff = (uint32_t)(((nw0 + (lane & 7) + ((lane >> 4) & 1) * 8) * ASTRIDE
                                + ((lane >> 3) & 1) * 8) * 2);

    float acc[2][8][4];
    #pragma unroll
    for (int mf = 0; mf < 2; mf++)
        #pragma unroll
        for (int nf = 0; nf < 8; nf++)
            #pragma unroll
            for (int v = 0; v < 4; v++) acc[mf][nf][v] = 0.f;

    const int NC = 9;
    #define GB_LOAD(c) do { \
        int st_ = (c) & 1; \
        uint32_t sA = sbase + st_ * GB_STG; \
        uint32_t sB = sA + GB_ABYTES; \
        int seg = (c) / 3, kc3 = (c) % 3; \
        const __nv_bfloat16* asrc = (seg == 1) ? &g_Wl[h][0][kc3 * 64] : &g_Wh[h][0][kc3 * 64]; \
        const __nv_bfloat16* bsrc; int brs; \
        if (kc3 < 2) { bsrc = (seg < 2) ? &g_ubh[h][n0][kc3 * 64] : &g_ubl[h][n0][kc3 * 64]; brs = 256; } \
        else         { bsrc = (seg < 2) ? &g_Hbh[h][n0][0] : &g_Hbl[h][n0][0]; brs = 128; } \
        _Pragma("unroll") \
        for (int it = 0; it < 4; it++) { \
            int idx = tid + 256 * it; \
            int row = idx >> 3, cu = idx & 7; \
            CP16(sA + row * (ASTRIDE * 2) + cu * 16, (const char*)asrc + row * 384 + cu * 16); \
        } \
        _Pragma("unroll") \
        for (int it = 0; it < 4; it++) { \
            int idx = tid + 256 * it; \
            int row = idx >> 3, cu = idx & 7; \
            CP16(sB + row * (ASTRIDE * 2) + cu * 16, (const char*)bsrc + row * brs + cu * 16); \
        } \
        CP_COMMIT(); \
    } while (0)

    GB_LOAD(0);
    #pragma unroll 1
    for (int c = 0; c < NC; c++) {
        if (c + 1 < NC) { GB_LOAD(c + 1); CP_WAIT1(); }
        else            { CP_WAIT0(); }
        __syncthreads();
        uint32_t sA = sbase + (c & 1) * GB_STG;
        uint32_t sB = sA + GB_ABYTES;
        uint32_t aAddr = sA + aOff;
        uint32_t bAddr = sB + bOff;
        #pragma unroll
        for (int ks = 0; ks < 4; ks++) {
            uint32_t afr[2][4];
            LDSM4(afr[0], aAddr + ks * 32);
            LDSM4(afr[1], aAddr + 16 * ASTRIDE * 2 + ks * 32);
            uint32_t bfr[4][4];
            #pragma unroll
            for (int p = 0; p < 4; p++)
                LDSM4(bfr[p], bAddr + p * 16 * ASTRIDE * 2 + ks * 32);
            #pragma unroll
            for (int p = 0; p < 4; p++)
                #pragma unroll
                for (int sub = 0; sub < 2; sub++) {
                    int nf = p * 2 + sub;
                    uint32_t b0 = bfr[p][sub * 2], b1 = bfr[p][sub * 2 + 1];
                    #pragma unroll
                    for (int mf = 0; mf < 2; mf++)
                        MMA16816(acc[mf][nf][0], acc[mf][nf][1], acc[mf][nf][2], acc[mf][nf][3],
                                 afr[mf][0], afr[mf][1], afr[mf][2], afr[mf][3], b0, b1);
                }
        }
        __syncthreads();
    }
    #undef GB_LOAD
    // epilogue -> y
    #pragma unroll
    for (int mf = 0; mf < 2; mf++) {
        int tau = m0 + mf * 16 + tg;
        #pragma unroll
        for (int nf = 0; nf < 8; nf++) {
            int n = n0 + nw0 + nf * 8 + tq * 2;
            int j = n >> 4, b = (n >> 2) & 3, r = n & 3;
            size_t base = ((size_t)(b * LL + j * CC + tau)) * DD + h * NH + r;
            *(float2*)&y[base]            = make_float2(acc[mf][nf][0], acc[mf][nf][1]);
            *(float2*)&y[base + 8 * DD]   = make_float2(acc[mf][nf][2], acc[mf][nf][3]);
        }
    }
}

// ---------------- launch ----------------
extern "C" void kernel_launch(void* const* d_in, const int* in_sizes, int n_in,
                              void* d_out, int out_size) {
    const float* u = (const float*)d_in[0];
    const float* a = (const float*)d_in[1];
    const float* b = (const float*)d_in[2];
    const float* c = (const float*)d_in[3];
    float* y = (float*)d_out;

    cudaFuncSetAttribute(k_gemm_g, cudaFuncAttributeMaxDynamicSharedMemorySize, GA_SMEM);
    cudaFuncSetAttribute(k_gemm_y, cudaFuncAttributeMaxDynamicSharedMemorySize, GB_SMEM);

    k_norm<<<NK, KD>>>(a);
    k_flag<<<1, NK>>>();
    k_precomp<<<NK, 256>>>(a, b, c);
    k_tr<<<2048, 256>>>(u);
    k_gemm_g<<<dim3(4, NK), 128, GA_SMEM>>>();
    k_scan<<<NK * 4, 64>>>();
    k_gemm_y<<<dim3(4, NK), 256, GB_SMEM>>>(y);
}